// round 2
// baseline (speedup 1.0000x reference)
#include <cuda_runtime.h>
#include <math.h>

typedef unsigned long long ull;

#define NN    800000
#define NF    100000
#define NR    2000
#define FEAT  86
#define H     128
#define SA    130   // activation tile row stride (even, padded)

// ---------------- device scratch (no runtime allocation allowed) ----------------
__device__ __align__(16) float g_root_emb[NR * H];
__device__ __align__(16) float g_frag_sum[(size_t)NF * H];
__device__ __align__(16) float g_cnt[NF];
__device__ __align__(16) float g_Wa[H * H];
__device__ __align__(16) float g_Wb[H * H];

// ---------------- f32x2 packed helpers (Blackwell FFMA2 path) ----------------
__device__ __forceinline__ ull pack2(float lo, float hi) {
    ull r; asm("mov.b64 %0, {%1, %2};" : "=l"(r) : "f"(lo), "f"(hi)); return r;
}
__device__ __forceinline__ void unpack2(ull v, float& lo, float& hi) {
    asm("mov.b64 {%0, %1}, %2;" : "=f"(lo), "=f"(hi) : "l"(v));
}
__device__ __forceinline__ void fma2(ull& d, ull a, ull b) {
    asm("fma.rn.f32x2 %0, %1, %2, %3;" : "=l"(d) : "l"(a), "l"(b), "l"(d));
}

// ---------------- shared 128x128 GEMM microkernel pieces ----------------
// Thread map: tx = tid&15 (columns), ty = tid>>4 (rows).
// Thread owns rows m = ty*8+i (i<8), column pairs n = 2*tx + 32*jj (jj<4).
// acc[i][jj] is the f32x2 (col n, col n+1) accumulator for row m.

__device__ __forceinline__ void acc_bias(ull acc[8][4], const float* __restrict__ bias, int tx) {
#pragma unroll
    for (int jj = 0; jj < 4; jj++) {
        float2 b = *(const float2*)(bias + 2 * tx + 32 * jj);
        ull p = pack2(b.x, b.y);
#pragma unroll
        for (int i = 0; i < 8; i++) acc[i][jj] = p;
    }
}

__device__ __forceinline__ void gemm_acc(ull acc[8][4], const float* __restrict__ sAct,
                                         const float* __restrict__ sW, int K, int tx, int ty) {
    const int rbase = ty * 8;
    const int cbase = 2 * tx;
#pragma unroll 2
    for (int k = 0; k < K; k++) {
        ull b2[4];
#pragma unroll
        for (int jj = 0; jj < 4; jj++)
            b2[jj] = *(const ull*)(sW + k * H + cbase + 32 * jj);
        const float* pA = sAct + rbase * SA + k;
#pragma unroll
        for (int i = 0; i < 8; i++) {
            float a = pA[i * SA];
            ull pa = pack2(a, a);
#pragma unroll
            for (int jj = 0; jj < 4; jj++) fma2(acc[i][jj], pa, b2[jj]);
        }
    }
}

__device__ __forceinline__ void write_act(ull acc[8][4], float* __restrict__ sAct,
                                          bool relu, int tx, int ty) {
#pragma unroll
    for (int i = 0; i < 8; i++) {
        int m = ty * 8 + i;
#pragma unroll
        for (int jj = 0; jj < 4; jj++) {
            float lo, hi; unpack2(acc[i][jj], lo, hi);
            if (relu) { lo = fmaxf(lo, 0.f); hi = fmaxf(hi, 0.f); }
            *(float2*)(sAct + m * SA + 2 * tx + 32 * jj) = make_float2(lo, hi);
        }
    }
}

// ---------------- kernel A: root encoder (tiny) ----------------
__global__ void root_enc_kernel(const float* __restrict__ root_repr,
                                const float* __restrict__ W_root,
                                const float* __restrict__ b_root) {
    __shared__ float sX[FEAT];
    int r = blockIdx.x, n = threadIdx.x;   // 128 threads
    for (int k = n; k < FEAT; k += 128) sX[k] = root_repr[r * FEAT + k];
    __syncthreads();
    float s = b_root[n];
#pragma unroll 2
    for (int k = 0; k < FEAT; k++) s += sX[k] * W_root[k * H + n];
    g_root_emb[r * H + n] = fmaxf(s, 0.f);
}

// ---------------- kernel: fold concat structure into combined weights ----------------
// cat = [ext, ext-mean, mean, onehot] @ W_m1  ==  ext@(W1a+W1b) + mean@(W1c-W1b) + W_m1[384+bk]
__global__ void combine_w_kernel(const float* __restrict__ W_m1) {
    int i = blockIdx.x * 256 + threadIdx.x;
    if (i < H * H) {
        float wb = W_m1[H * H + i];
        g_Wa[i] = W_m1[i] + wb;
        g_Wb[i] = W_m1[2 * H * H + i] - wb;
    }
}

// ---------------- kernel B: fused node chain + segmented pooling ----------------
__global__ __launch_bounds__(256, 1) void node_chain_kernel(
    const float* __restrict__ node_h, const int* __restrict__ seg,
    const float* __restrict__ W_in, const float* __restrict__ b_in,
    const float* __restrict__ W_g1, const float* __restrict__ b_g1,
    const float* __restrict__ W_g2, const float* __restrict__ b_g2) {
    extern __shared__ float sm[];
    float* sAct = sm;            // 128 x SA
    float* sW   = sm + H * SA;   // 128 x 128
    __shared__ int sSeg[128];

    int tid = threadIdx.x;
    int base = blockIdx.x * 128;   // NN = 6250 * 128 exactly

    // load X tile (coalesced global reads)
    for (int idx = tid; idx < 128 * FEAT; idx += 256) {
        int m = idx / FEAT, k = idx - m * FEAT;
        sAct[m * SA + k] = node_h[(base + m) * FEAT + k];
    }
    if (tid < 128) sSeg[tid] = seg[base + tid];
    {   // load W_in
        const float4* s = (const float4*)W_in; float4* d = (float4*)sW;
        for (int idx = tid; idx < FEAT * (H / 4); idx += 256) d[idx] = s[idx];
    }
    __syncthreads();

    int tx = tid & 15, ty = tid >> 4;
    ull acc[8][4];

    // layer 1: x @ W_in + b_in   (no relu)
    acc_bias(acc, b_in, tx);
    gemm_acc(acc, sAct, sW, FEAT, tx, ty);
    __syncthreads();
    write_act(acc, sAct, false, tx, ty);
    {   const float4* s = (const float4*)W_g1; float4* d = (float4*)sW;
        for (int idx = tid; idx < H * (H / 4); idx += 256) d[idx] = s[idx]; }
    __syncthreads();

    // layer 2: relu(h @ W_g1 + b_g1)
    acc_bias(acc, b_g1, tx);
    gemm_acc(acc, sAct, sW, H, tx, ty);
    __syncthreads();
    write_act(acc, sAct, true, tx, ty);
    {   const float4* s = (const float4*)W_g2; float4* d = (float4*)sW;
        for (int idx = tid; idx < H * (H / 4); idx += 256) d[idx] = s[idx]; }
    __syncthreads();

    // layer 3: relu(h @ W_g2 + b_g2)
    acc_bias(acc, b_g2, tx);
    gemm_acc(acc, sAct, sW, H, tx, ty);
    __syncthreads();
    write_act(acc, sAct, true, tx, ty);
    __syncthreads();

    // segmented pooling: segment_ids are sorted -> run-length reduce in-CTA,
    // one atomic per (segment, col) run boundary (~16 frags per 128-node tile).
    if (tid < 128) {
        int n = tid;
        float r = 0.f; int cur = sSeg[0];
        for (int m = 0; m < 128; m++) {
            int s = sSeg[m];
            if (s != cur) { atomicAdd(&g_frag_sum[(size_t)cur * H + n], r); r = 0.f; cur = s; }
            r += sAct[m * SA + n];
        }
        atomicAdd(&g_frag_sum[(size_t)cur * H + n], r);
    } else if (tid == 128) {
        float c = 0.f; int cur = sSeg[0];
        for (int m = 0; m < 128; m++) {
            int s = sSeg[m];
            if (s != cur) { atomicAdd(&g_cnt[cur], c); c = 0.f; cur = s; }
            c += 1.f;
        }
        atomicAdd(&g_cnt[cur], c);
    }
}

// ---------------- kernel C: fragment MLP head ----------------
__global__ __launch_bounds__(256, 1) void frag_mlp_kernel(
    const int* __restrict__ ind_maps, const int* __restrict__ broken,
    const float* __restrict__ W_m1, const float* __restrict__ b_m1,
    const float* __restrict__ W_m2, const float* __restrict__ b_m2,
    const float* __restrict__ W_out, const float* __restrict__ b_out,
    const float* __restrict__ W_attn, const float* __restrict__ b_attn,
    float* __restrict__ out) {
    extern __shared__ float sm[];
    float* sAct = sm;
    float* sW   = sm + H * SA;
    __shared__ int sInd[128];
    __shared__ float sInv[128];
    __shared__ int sBk[128];
    __shared__ float sBo[26];

    int tid = threadIdx.x;
    int base = blockIdx.x * 128;
    int valid = NF - base; if (valid > 128) valid = 128;

    if (tid < 128) {
        int f = base + tid;
        if (f < NF) {
            sInd[tid] = ind_maps[f];
            sInv[tid] = 1.f / fmaxf(g_cnt[f], 1.f);
            int b = broken[f];
            sBk[tid] = min(max(b, 0), 12);
        } else { sInd[tid] = 0; sInv[tid] = 0.f; sBk[tid] = 0; }
    }
    if (tid < 26) sBo[tid] = (tid < 13) ? b_out[tid] : b_attn[tid - 13];
    __syncthreads();

    // stage ext-root tile + Wa
    for (int idx = tid; idx < 128 * H; idx += 256) {
        int m = idx >> 7, n = idx & 127;
        sAct[m * SA + n] = g_root_emb[sInd[m] * H + n];
    }
    {   const float4* s = (const float4*)g_Wa; float4* d = (float4*)sW;
        for (int idx = tid; idx < H * (H / 4); idx += 256) d[idx] = s[idx]; }
    __syncthreads();

    int tx = tid & 15, ty = tid >> 4;
    ull acc[8][4];

    // layer1 pass 1: ext @ Wa  (+ b_m1)
    acc_bias(acc, b_m1, tx);
    gemm_acc(acc, sAct, sW, H, tx, ty);
    __syncthreads();

    // stage mean tile + Wb
    for (int idx = tid; idx < 128 * H; idx += 256) {
        int m = idx >> 7, n = idx & 127;
        int f = base + m;
        sAct[m * SA + n] = (f < NF) ? g_frag_sum[(size_t)f * H + n] * sInv[m] : 0.f;
    }
    {   const float4* s = (const float4*)g_Wb; float4* d = (float4*)sW;
        for (int idx = tid; idx < H * (H / 4); idx += 256) d[idx] = s[idx]; }
    __syncthreads();

    // layer1 pass 2: += mean @ Wb
    gemm_acc(acc, sAct, sW, H, tx, ty);
    __syncthreads();

    // + one-hot row of W_m1, relu, write H1
#pragma unroll
    for (int i = 0; i < 8; i++) {
        int m = ty * 8 + i;
        const float* wr = W_m1 + (size_t)(384 + sBk[m]) * H;
#pragma unroll
        for (int jj = 0; jj < 4; jj++) {
            int n = 2 * tx + 32 * jj;
            float lo, hi; unpack2(acc[i][jj], lo, hi);
            lo = fmaxf(lo + wr[n], 0.f);
            hi = fmaxf(hi + wr[n + 1], 0.f);
            *(float2*)(sAct + m * SA + n) = make_float2(lo, hi);
        }
    }
    {   const float4* s = (const float4*)W_m2; float4* d = (float4*)sW;
        for (int idx = tid; idx < H * (H / 4); idx += 256) d[idx] = s[idx]; }
    __syncthreads();

    // layer2: relu(H1 @ W_m2 + b_m2)
    acc_bias(acc, b_m2, tx);
    gemm_acc(acc, sAct, sW, H, tx, ty);
    __syncthreads();
    write_act(acc, sAct, true, tx, ty);

    // build combined output weights [k][26] = [W_out | W_attn]
    for (int idx = tid; idx < H * 13; idx += 256) {
        int k = idx / 13, c = idx - 13 * k;
        sW[k * 26 + c]      = W_out[idx];
        sW[k * 26 + 13 + c] = W_attn[idx];
    }
    __syncthreads();

    // output layer: 26 columns (13 sigmoid + 13 linear)
    for (int o = tid; o < 128 * 26; o += 256) {
        int m = o / 26, c = o - 26 * m;
        if (m < valid) {
            float s = sBo[c];
            const float* h = sAct + m * SA;
#pragma unroll 4
            for (int k = 0; k < H; k++) s += h[k] * sW[k * 26 + c];
            int f = base + m;
            if (c < 13) out[f * 13 + c] = 1.f / (1.f + __expf(-s));
            else        out[(size_t)NF * 13 + f * 13 + (c - 13)] = s;
        }
    }
}

// ---------------- launcher ----------------
extern "C" void kernel_launch(void* const* d_in, const int* in_sizes, int n_in,
                              void* d_out, int out_size) {
    const float* node_h    = (const float*)d_in[0];
    const int*   seg       = (const int*)d_in[1];
    const float* root_repr = (const float*)d_in[2];
    const int*   ind_maps  = (const int*)d_in[3];
    const int*   broken    = (const int*)d_in[4];
    const float* W_root = (const float*)d_in[5];  const float* b_root = (const float*)d_in[6];
    const float* W_in   = (const float*)d_in[7];  const float* b_in   = (const float*)d_in[8];
    const float* W_g1   = (const float*)d_in[9];  const float* b_g1   = (const float*)d_in[10];
    const float* W_g2   = (const float*)d_in[11]; const float* b_g2   = (const float*)d_in[12];
    const float* W_m1   = (const float*)d_in[13]; const float* b_m1   = (const float*)d_in[14];
    const float* W_m2   = (const float*)d_in[15]; const float* b_m2   = (const float*)d_in[16];
    const float* W_out  = (const float*)d_in[17]; const float* b_out  = (const float*)d_in[18];
    const float* W_attn = (const float*)d_in[19]; const float* b_attn = (const float*)d_in[20];
    float* out = (float*)d_out;

    void* p_fs = nullptr; void* p_cnt = nullptr;
    cudaGetSymbolAddress(&p_fs, g_frag_sum);
    cudaGetSymbolAddress(&p_cnt, g_cnt);
    cudaMemsetAsync(p_fs, 0, (size_t)NF * H * sizeof(float), 0);
    cudaMemsetAsync(p_cnt, 0, (size_t)NF * sizeof(float), 0);

    int smem = (H * SA + H * H) * (int)sizeof(float);   // ~132 KB
    cudaFuncSetAttribute(node_chain_kernel, cudaFuncAttributeMaxDynamicSharedMemorySize, smem);
    cudaFuncSetAttribute(frag_mlp_kernel,   cudaFuncAttributeMaxDynamicSharedMemorySize, smem);

    root_enc_kernel<<<NR, 128>>>(root_repr, W_root, b_root);
    combine_w_kernel<<<(H * H + 255) / 256, 256>>>(W_m1);
    node_chain_kernel<<<NN / 128, 256, smem>>>(node_h, seg, W_in, b_in, W_g1, b_g1, W_g2, b_g2);
    frag_mlp_kernel<<<(NF + 127) / 128, 256, smem>>>(ind_maps, broken, W_m1, b_m1,
                                                     W_m2, b_m2, W_out, b_out,
                                                     W_attn, b_attn, out);
}